// round 6
// baseline (speedup 1.0000x reference)
#include <cuda_runtime.h>
#include <cstdint>

// ---------------------------------------------------------------------------
// params: g_params = { a_off, a_dmo } with
//   a_off = -p_off/ln2 , a_dmo = -abar/ln2
// so that w = p/(-ln u) = fma(av, a_dmo, a_off) / log2(u)   (both negative)
// ---------------------------------------------------------------------------
__device__ float g_params[2];
__device__ uint32_t g_one;   // runtime 1, opaque to ptxas

__global__ void abar_kernel(const float* __restrict__ beta,
                            const int* __restrict__ t_ptr) {
    int t = *t_ptr;
    int lane = threadIdx.x;  // 32 threads
    float prod = 1.0f;
    for (int i = lane; i < t; i += 32) prod *= (1.0f - beta[i]);
#pragma unroll
    for (int d = 16; d > 0; d >>= 1)
        prod *= __shfl_xor_sync(0xFFFFFFFFu, prod, d);
    if (lane == 0) {
        float abar = prod;
        float p_off = (1.0f - abar) * (1.0f / 256.0f);   // (1-abar)/K
        const float inv_ln2 = 1.4426950408889634f;
        g_params[0] = -p_off * inv_ln2;
        g_params[1] = -abar * inv_ln2;    // -(p_diag - p_off)/ln2
        g_one = (t < 1000000000) ? 1u : 2u;  // always 1 at runtime
    }
}

// ---------------------------------------------------------------------------
// threefry2x32, 20 rounds, key = (0,1)  (jax.random.key(1)).
// Partitionable layout: element i -> counter (0, i), output = o0 ^ o1.
// The x0-chain round adds are forced onto the IMAD/FMA pipe (mad.lo with a
// runtime-opaque multiplier == 1); rotates/xors stay on the alu pipe; the
// x1 key injections stay natural so the serial x1 path has no cross-pipe hop.
// ---------------------------------------------------------------------------
__device__ __forceinline__ uint32_t rotl32(uint32_t x, int d) {
    return __funnelshift_l(x, x, d);
}

// d = a*one + b with one==1 -> routed to the fma pipe as IMAD
__device__ __forceinline__ uint32_t madd(uint32_t a, uint32_t b, uint32_t one) {
    uint32_t r;
    asm("mad.lo.u32 %0, %1, %2, %3;" : "=r"(r) : "r"(a), "r"(one), "r"(b));
    return r;
}

__device__ __forceinline__ uint32_t threefry01_xor(uint32_t c1, uint32_t one) {
    const uint32_t ks2 = 0x1BD11BDBu;  // 0x1BD11BDA ^ 0 ^ 1
    // x0 = 0 + ks0 = 0 ; x1 = c1 + ks1 = c1 + 1 ; round 1: x0 += x1 -> x0 = x1
    uint32_t x1 = c1 + 1u;
    uint32_t x0 = x1;
    x1 = rotl32(x1, 13); x1 ^= x0;
#define TF_RND(R) { x0 = madd(x1, x0, one); x1 = rotl32(x1, R); x1 ^= x0; }
    TF_RND(15) TF_RND(26) TF_RND(6)
    x0 += 1u;                 // += ks1   (x0-side injection, off x1 path)
    x1 += ks2 + 1u;           // += ks2+1 (x1 path: plain add, no pipe hop)
    TF_RND(17) TF_RND(29) TF_RND(16) TF_RND(24)
    x0 += ks2;
    x1 += 2u;
    TF_RND(13) TF_RND(15) TF_RND(26) TF_RND(6)
    /* x0 += ks0 (= 0): no-op */
    x1 += 4u;
    TF_RND(17) TF_RND(29) TF_RND(16) TF_RND(24)
    x0 += 1u;
    x1 += ks2 + 4u;
    TF_RND(13) TF_RND(15) TF_RND(26) TF_RND(6)
    x0 += ks2;
    x1 += 5u;
#undef TF_RND
    return x0 ^ x1;
}

// jax uniform, bit-exact: u = rn( (bits>>9) * 2^-23 + 1e-9 )
__device__ __forceinline__ float bits_to_u(uint32_t b) {
    return fmaf(__uint2float_rn(b >> 9), 0x1p-23f, 1e-9f);
}

// ---------------------------------------------------------------------------
// Main kernel: one warp per pixel. 256 channels -> 8 per lane (2x float4).
// 8 independent threefry chains first (ILP-8), then float epilogue.
// ---------------------------------------------------------------------------
__global__ __launch_bounds__(256, 4)
void gumbel_softmax_kernel(const float4* __restrict__ x0,
                           float4* __restrict__ out) {
    const int pixel = (blockIdx.x * blockDim.x + threadIdx.x) >> 5;  // [0,131072)
    const int lane = threadIdx.x & 31;

    const float a_off = g_params[0];   // -p_off/ln2
    const float a_dmo = g_params[1];   // -abar/ln2
    const uint32_t one = g_one;

    // loads first
    const float4 a0 = x0[pixel * 64 + lane];
    const float4 a1 = x0[pixel * 64 + lane + 32];

    // 8 independent threefry chains
    const uint32_t base = ((uint32_t)pixel << 8) + ((uint32_t)lane << 2);
    uint32_t bits[8];
#pragma unroll
    for (int n = 0; n < 8; n++) {
        const uint32_t ctr = base + (uint32_t)((n >> 2) * 128 + (n & 3));
        bits[n] = threefry01_xor(ctr, one);
    }

    // float epilogue
    const float av[8] = {a0.x, a0.y, a0.z, a0.w, a1.x, a1.y, a1.z, a1.w};
    float w[8];
    float s = 0.0f;
#pragma unroll
    for (int n = 0; n < 8; n++) {
        float lg = __log2f(bits_to_u(bits[n]));        // < 0
        float npv = fmaf(av[n], a_dmo, a_off);         // < 0
        float wv = __fdividef(npv, lg);                // > 0
        w[n] = wv;
        s += wv;
    }

#pragma unroll
    for (int d = 16; d > 0; d >>= 1)
        s += __shfl_xor_sync(0xFFFFFFFFu, s, d);
    const float inv = __fdividef(1.0f, s);

    float4 o0, o1;
    o0.x = w[0] * inv; o0.y = w[1] * inv; o0.z = w[2] * inv; o0.w = w[3] * inv;
    o1.x = w[4] * inv; o1.y = w[5] * inv; o1.z = w[6] * inv; o1.w = w[7] * inv;
    out[pixel * 64 + lane]      = o0;
    out[pixel * 64 + lane + 32] = o1;
}

// ---------------------------------------------------------------------------
extern "C" void kernel_launch(void* const* d_in, const int* in_sizes, int n_in,
                              void* d_out, int out_size) {
    const float* x0   = (const float*)d_in[0];
    const float* beta = (const float*)d_in[1];
    const int*   t    = (const int*)d_in[2];
    float* out = (float*)d_out;

    abar_kernel<<<1, 32>>>(beta, t);
    // 131072 pixels -> 131072 warps -> 16384 blocks of 256 threads
    gumbel_softmax_kernel<<<16384, 256>>>((const float4*)x0, (float4*)out);
}